// round 7
// baseline (speedup 1.0000x reference)
#include <cuda_runtime.h>

#define B_   4
#define S_   2048
#define H_   16
#define HID_ 2048
#define DK_  128
#define DV_  128
#define P_   (B_*S_)   // 8192 positions

// scratch (allowed: __device__ globals)
__device__ float g_decay[P_*H_];
__device__ float g_beta [P_*H_];

// ============================================================
// Kernel 1: gating GEMM  raw = x @ [Wa;Wb]^T  + epilogue
// ============================================================
#define GT_POS 64
#define GT_K   32

__global__ __launch_bounds__(256) void gate_kernel(
    const float* __restrict__ x,
    const float* __restrict__ Wa, const float* __restrict__ Wb,
    const float* __restrict__ dt_bias, const float* __restrict__ A_log)
{
    __shared__ float xs[GT_POS][GT_K+1];
    __shared__ float ws[32][GT_K+1];
    int t  = threadIdx.x;
    int p0 = blockIdx.x * GT_POS;
    int tx = t & 7;
    int ty = t >> 3;
    float acc[2][4] = {};

    for (int kc = 0; kc < HID_; kc += GT_K) {
        #pragma unroll
        for (int i = 0; i < (GT_POS*GT_K)/256; ++i) {
            int e = i*256 + t; int r = e >> 5, c = e & 31;
            xs[r][c] = x[(size_t)(p0 + r)*HID_ + kc + c];
        }
        #pragma unroll
        for (int i = 0; i < (32*GT_K)/256; ++i) {
            int e = i*256 + t; int f = e >> 5, c = e & 31;
            const float* wrow = (f < 16) ? (Wa + f*HID_) : (Wb + (f-16)*HID_);
            ws[f][c] = wrow[kc + c];
        }
        __syncthreads();
        #pragma unroll
        for (int k = 0; k < GT_K; ++k) {
            float xv0 = xs[2*ty  ][k];
            float xv1 = xs[2*ty+1][k];
            #pragma unroll
            for (int j = 0; j < 4; ++j) {
                float wv = ws[4*tx+j][k];
                acc[0][j] = fmaf(xv0, wv, acc[0][j]);
                acc[1][j] = fmaf(xv1, wv, acc[1][j]);
            }
        }
        __syncthreads();
    }

    #pragma unroll
    for (int i = 0; i < 2; ++i) {
        int p = p0 + 2*ty + i;
        #pragma unroll
        for (int j = 0; j < 4; ++j) {
            int f = 4*tx + j;
            float r = acc[i][j];
            if (f < 16) {
                float z  = r + __ldg(dt_bias + f);
                float sp = fmaxf(z, 0.0f) + log1pf(expf(-fabsf(z)));
                g_decay[p*H_ + f] = expf(-expf(__ldg(A_log + f)) * sp);
            } else {
                g_beta[p*H_ + (f-16)] = r;
            }
        }
    }
}

// ============================================================
// Kernel 2: delta-rule scan, column-owning lanes.
// CTA = 256 thr = (b, h, 64 DV cols) -> 128 CTAs (~1/SM).
// Warp covers 8 cols; 4 sub-lanes per col, each owning 32
// contiguous DK rows (16 f32x2 regs of state) and loading ITS
// OWN 128B slice of k and q (LDG dedup/L1-hit across dup lanes
// and sibling warps). No gather shuffles.
// Per step:  p = redux4(k . S[:,col]) ;  d = (v - g*p)*beta ;
//            S = g*S + k (x) d ;  out = redux4(q . S_new[:,col])
// redux4 = xor1 + xor2 butterfly (2 SHFL for all 8 cols at once).
// ============================================================
typedef unsigned long long u64;

__device__ __forceinline__ u64 fma2(u64 a, u64 b, u64 c) {
    u64 d; asm("fma.rn.f32x2 %0, %1, %2, %3;" : "=l"(d) : "l"(a), "l"(b), "l"(c));
    return d;
}
__device__ __forceinline__ u64 mul2(u64 a, u64 b) {
    u64 d; asm("mul.rn.f32x2 %0, %1, %2;" : "=l"(d) : "l"(a), "l"(b));
    return d;
}
__device__ __forceinline__ u64 add2(u64 a, u64 b) {
    u64 d; asm("add.rn.f32x2 %0, %1, %2;" : "=l"(d) : "l"(a), "l"(b));
    return d;
}
__device__ __forceinline__ u64 pack2(float x, float y) {
    u64 d; asm("mov.b64 %0, {%1, %2};" : "=l"(d)
               : "r"(__float_as_uint(x)), "r"(__float_as_uint(y)));
    return d;
}
__device__ __forceinline__ float hadd2(u64 a) {
    unsigned lo, hi;
    asm("mov.b64 {%0, %1}, %2;" : "=r"(lo), "=r"(hi) : "l"(a));
    return __uint_as_float(lo) + __uint_as_float(hi);
}

struct Buf {
    u64 kk[16], qq[16];   // lane's 32 rows of k and q (f32x2 pairs)
    float v, g, b;
};

__device__ __forceinline__ void load_buf(Buf& d,
    const float* kb, const float* qb, const float* vb,
    const float* gb, const float* bb, int s, int sub, int col)
{
    size_t off = (size_t)s * (H_*DK_);
    const ulonglong2* kp = (const ulonglong2*)(kb + off + sub*32);
    const ulonglong2* qp = (const ulonglong2*)(qb + off + sub*32);
    #pragma unroll
    for (int i = 0; i < 8; ++i) {
        ulonglong2 t = __ldg(kp + i);
        d.kk[2*i] = t.x; d.kk[2*i+1] = t.y;
    }
    #pragma unroll
    for (int i = 0; i < 8; ++i) {
        ulonglong2 t = __ldg(qp + i);
        d.qq[2*i] = t.x; d.qq[2*i+1] = t.y;
    }
    d.v = __ldg(vb + off + col);
    d.g = __ldg(gb + (size_t)s*H_);
    d.b = __ldg(bb + (size_t)s*H_);
}

__device__ __forceinline__ void do_step(const Buf& c, u64 st[16],
                                        float* outp, int sub, int col)
{
    const unsigned FM = 0xffffffffu;
    // ---- p = k . S[:,col], 4-accumulator tree ----
    u64 a0 = mul2(c.kk[0], st[0]);
    u64 a1 = mul2(c.kk[1], st[1]);
    u64 a2 = mul2(c.kk[2], st[2]);
    u64 a3 = mul2(c.kk[3], st[3]);
    #pragma unroll
    for (int j = 4; j < 16; j += 4) {
        a0 = fma2(c.kk[j+0], st[j+0], a0);
        a1 = fma2(c.kk[j+1], st[j+1], a1);
        a2 = fma2(c.kk[j+2], st[j+2], a2);
        a3 = fma2(c.kk[j+3], st[j+3], a3);
    }
    float p = hadd2(add2(add2(a0, a1), add2(a2, a3)));
    p += __shfl_xor_sync(FM, p, 1);
    p += __shfl_xor_sync(FM, p, 2);

    // ---- delta ----
    float g = c.g;
    float d = fmaf(-g, p, c.v) * c.b;

    // ---- state update: S = g*S + k (x) d ----
    u64 gp = pack2(g, g), dp = pack2(d, d);
    #pragma unroll
    for (int j = 0; j < 16; ++j)
        st[j] = fma2(c.kk[j], dp, mul2(gp, st[j]));

    // ---- out = q . S_new[:,col] ----
    u64 b0 = mul2(c.qq[0], st[0]);
    u64 b1 = mul2(c.qq[1], st[1]);
    u64 b2 = mul2(c.qq[2], st[2]);
    u64 b3 = mul2(c.qq[3], st[3]);
    #pragma unroll
    for (int j = 4; j < 16; j += 4) {
        b0 = fma2(c.qq[j+0], st[j+0], b0);
        b1 = fma2(c.qq[j+1], st[j+1], b1);
        b2 = fma2(c.qq[j+2], st[j+2], b2);
        b3 = fma2(c.qq[j+3], st[j+3], b3);
    }
    float o = hadd2(add2(add2(b0, b1), add2(b2, b3)));
    o += __shfl_xor_sync(FM, o, 1);
    o += __shfl_xor_sync(FM, o, 2);

    if (sub == 0)
        outp[col] = o;
}

__global__ void __launch_bounds__(256, 1) scan_kernel(
    const float* __restrict__ q, const float* __restrict__ k,
    const float* __restrict__ v, float* __restrict__ out)
{
    int cta  = blockIdx.x;        // 128 CTAs
    int bh   = cta >> 1;
    int half = cta & 1;
    int b    = bh >> 4, h = bh & 15;
    int tid  = threadIdx.x;
    int w    = tid >> 5;
    int lane = tid & 31;
    int colL = lane >> 2;         // 0..7 within warp
    int sub  = lane & 3;          // 0..3 row-slice within col
    int col  = half*64 + w*8 + colL;

    size_t base = ((size_t)b * S_ * H_ + h) * DK_;
    const float* kb = k + base;
    const float* qb = q + base;
    const float* vb = v + base;
    float*       ob = out + base;
    const float* gb = g_decay + (size_t)b * S_ * H_ + h;
    const float* bb = g_beta  + (size_t)b * S_ * H_ + h;

    u64 st[16];
    #pragma unroll
    for (int j = 0; j < 16; ++j) st[j] = 0ull;

    Buf A, Bf;
    load_buf(A, kb, qb, vb, gb, bb, 0, sub, col);

    for (int s = 0; s < S_; s += 2) {
        load_buf(Bf, kb, qb, vb, gb, bb, s+1, sub, col);
        do_step(A, st, ob + (size_t)s*(H_*DV_), sub, col);
        int i2 = (s+2 < S_) ? s+2 : S_-1;
        load_buf(A, kb, qb, vb, gb, bb, i2, sub, col);
        do_step(Bf, st, ob + (size_t)(s+1)*(H_*DV_), sub, col);
    }
}

// ============================================================
extern "C" void kernel_launch(void* const* d_in, const int* in_sizes, int n_in,
                              void* d_out, int out_size)
{
    (void)in_sizes; (void)n_in; (void)out_size;
    const float* x   = (const float*)d_in[0];
    const float* q   = (const float*)d_in[1];
    const float* k   = (const float*)d_in[2];
    const float* v   = (const float*)d_in[3];
    const float* Wa  = (const float*)d_in[4];
    const float* Wb  = (const float*)d_in[5];
    const float* dtb = (const float*)d_in[6];
    const float* Al  = (const float*)d_in[7];
    float* out = (float*)d_out;

    gate_kernel<<<P_/GT_POS, 256>>>(x, Wa, Wb, dtb, Al);
    scan_kernel<<<B_*H_*2, 256>>>(q, k, v, out);
}

// round 8
// speedup vs baseline: 1.5719x; 1.5719x over previous
#include <cuda_runtime.h>

#define B_   4
#define S_   2048
#define H_   16
#define HID_ 2048
#define DK_  128
#define DV_  128
#define P_   (B_*S_)   // 8192 positions

// scratch (allowed: __device__ globals)
__device__ float g_decay[P_*H_];
__device__ float g_beta [P_*H_];

// ============================================================
// Kernel 1: gating GEMM  raw = x @ [Wa;Wb]^T  + epilogue
// ============================================================
#define GT_POS 64
#define GT_K   32

__global__ __launch_bounds__(256) void gate_kernel(
    const float* __restrict__ x,
    const float* __restrict__ Wa, const float* __restrict__ Wb,
    const float* __restrict__ dt_bias, const float* __restrict__ A_log)
{
    __shared__ float xs[GT_POS][GT_K+1];
    __shared__ float ws[32][GT_K+1];
    int t  = threadIdx.x;
    int p0 = blockIdx.x * GT_POS;
    int tx = t & 7;
    int ty = t >> 3;
    float acc[2][4] = {};

    for (int kc = 0; kc < HID_; kc += GT_K) {
        #pragma unroll
        for (int i = 0; i < (GT_POS*GT_K)/256; ++i) {
            int e = i*256 + t; int r = e >> 5, c = e & 31;
            xs[r][c] = x[(size_t)(p0 + r)*HID_ + kc + c];
        }
        #pragma unroll
        for (int i = 0; i < (32*GT_K)/256; ++i) {
            int e = i*256 + t; int f = e >> 5, c = e & 31;
            const float* wrow = (f < 16) ? (Wa + f*HID_) : (Wb + (f-16)*HID_);
            ws[f][c] = wrow[kc + c];
        }
        __syncthreads();
        #pragma unroll
        for (int k = 0; k < GT_K; ++k) {
            float xv0 = xs[2*ty  ][k];
            float xv1 = xs[2*ty+1][k];
            #pragma unroll
            for (int j = 0; j < 4; ++j) {
                float wv = ws[4*tx+j][k];
                acc[0][j] = fmaf(xv0, wv, acc[0][j]);
                acc[1][j] = fmaf(xv1, wv, acc[1][j]);
            }
        }
        __syncthreads();
    }

    #pragma unroll
    for (int i = 0; i < 2; ++i) {
        int p = p0 + 2*ty + i;
        #pragma unroll
        for (int j = 0; j < 4; ++j) {
            int f = 4*tx + j;
            float r = acc[i][j];
            if (f < 16) {
                float z  = r + __ldg(dt_bias + f);
                float sp = fmaxf(z, 0.0f) + log1pf(expf(-fabsf(z)));
                g_decay[p*H_ + f] = expf(-expf(__ldg(A_log + f)) * sp);
            } else {
                g_beta[p*H_ + (f-16)] = r;
            }
        }
    }
}

// ============================================================
// Kernel 2: delta-rule scan, column-owning lanes, interleaved rows.
// Warp per (b,h, 8 DV cols): grid 1024 x 32 threads.
// lane = (colowner = lane>>2, sub = lane&3). Lane owns DV column
// col = colg*8 + colowner and row chunks {j*16 + sub*4 .. +4},
// j=0..7 (16 f32x2 regs of state). LDG.128 j loads bytes
// [j*64 + sub*16, +16): warp addresses = one contiguous 64B
// region duplicated across the 8 colowners -> ~1 wavefront.
// Per step:
//   p = redux4( k . S[:,col] )      (xor1 + xor2)
//   d = (v - g*p) * beta
//   S = g*S + k (x) d
//   o = redux4( q . S_new[:,col] )  (off recurrence path)
// ============================================================
typedef unsigned long long u64;

__device__ __forceinline__ u64 fma2(u64 a, u64 b, u64 c) {
    u64 d; asm("fma.rn.f32x2 %0, %1, %2, %3;" : "=l"(d) : "l"(a), "l"(b), "l"(c));
    return d;
}
__device__ __forceinline__ u64 mul2(u64 a, u64 b) {
    u64 d; asm("mul.rn.f32x2 %0, %1, %2;" : "=l"(d) : "l"(a), "l"(b));
    return d;
}
__device__ __forceinline__ u64 add2(u64 a, u64 b) {
    u64 d; asm("add.rn.f32x2 %0, %1, %2;" : "=l"(d) : "l"(a), "l"(b));
    return d;
}
__device__ __forceinline__ u64 pack2(float x, float y) {
    u64 d; asm("mov.b64 %0, {%1, %2};" : "=l"(d)
               : "r"(__float_as_uint(x)), "r"(__float_as_uint(y)));
    return d;
}
__device__ __forceinline__ float hadd2(u64 a) {
    unsigned lo, hi;
    asm("mov.b64 {%0, %1}, %2;" : "=r"(lo), "=r"(hi) : "l"(a));
    return __uint_as_float(lo) + __uint_as_float(hi);
}

struct Buf {
    u64 kk[16], qq[16];   // lane's 32 interleaved rows of k and q
    float v, g, b;
};

__device__ __forceinline__ void load_buf(Buf& d,
    const float* kb, const float* qb, const float* vb,
    const float* gb, const float* bb, int s, int sub, int col)
{
    size_t off = (size_t)s * (H_*DK_);
    #pragma unroll
    for (int j = 0; j < 8; ++j) {
        ulonglong2 t = __ldg((const ulonglong2*)(kb + off + j*16 + sub*4));
        d.kk[2*j] = t.x; d.kk[2*j+1] = t.y;
    }
    #pragma unroll
    for (int j = 0; j < 8; ++j) {
        ulonglong2 t = __ldg((const ulonglong2*)(qb + off + j*16 + sub*4));
        d.qq[2*j] = t.x; d.qq[2*j+1] = t.y;
    }
    d.v = __ldg(vb + off + col);
    d.g = __ldg(gb + (size_t)s*H_);
    d.b = __ldg(bb + (size_t)s*H_);
}

__device__ __forceinline__ void do_step(const Buf& c, u64 st[16],
                                        float* outp, int sub, int col)
{
    const unsigned FM = 0xffffffffu;
    // ---- p = k . S[:,col], 4-accumulator tree ----
    u64 a0 = mul2(c.kk[0], st[0]);
    u64 a1 = mul2(c.kk[1], st[1]);
    u64 a2 = mul2(c.kk[2], st[2]);
    u64 a3 = mul2(c.kk[3], st[3]);
    #pragma unroll
    for (int j = 4; j < 16; j += 4) {
        a0 = fma2(c.kk[j+0], st[j+0], a0);
        a1 = fma2(c.kk[j+1], st[j+1], a1);
        a2 = fma2(c.kk[j+2], st[j+2], a2);
        a3 = fma2(c.kk[j+3], st[j+3], a3);
    }
    float p = hadd2(add2(add2(a0, a1), add2(a2, a3)));
    p += __shfl_xor_sync(FM, p, 1);
    p += __shfl_xor_sync(FM, p, 2);

    // ---- delta ----
    float g = c.g;
    float d = fmaf(-g, p, c.v) * c.b;

    // ---- state update: S = g*S + k (x) d ----
    u64 gp = pack2(g, g), dp = pack2(d, d);
    #pragma unroll
    for (int j = 0; j < 16; ++j)
        st[j] = fma2(c.kk[j], dp, mul2(gp, st[j]));

    // ---- out = q . S_new[:,col] (off recurrence critical path) ----
    u64 b0 = mul2(c.qq[0], st[0]);
    u64 b1 = mul2(c.qq[1], st[1]);
    u64 b2 = mul2(c.qq[2], st[2]);
    u64 b3 = mul2(c.qq[3], st[3]);
    #pragma unroll
    for (int j = 4; j < 16; j += 4) {
        b0 = fma2(c.qq[j+0], st[j+0], b0);
        b1 = fma2(c.qq[j+1], st[j+1], b1);
        b2 = fma2(c.qq[j+2], st[j+2], b2);
        b3 = fma2(c.qq[j+3], st[j+3], b3);
    }
    float o = hadd2(add2(add2(b0, b1), add2(b2, b3)));
    o += __shfl_xor_sync(FM, o, 1);
    o += __shfl_xor_sync(FM, o, 2);

    if (sub == 0)
        outp[col] = o;
}

__global__ void __launch_bounds__(32) scan_kernel(
    const float* __restrict__ q, const float* __restrict__ k,
    const float* __restrict__ v, float* __restrict__ out)
{
    int bid  = blockIdx.x;        // 1024 warps
    int colg = bid & 15;          // 16 column groups of 8
    int bh   = bid >> 4;
    int b    = bh >> 4, h = bh & 15;
    int lane = threadIdx.x;
    int colowner = lane >> 2;     // 0..7
    int sub  = lane & 3;          // 0..3 interleaved row slice
    int col  = colg*8 + colowner;

    size_t base = ((size_t)b * S_ * H_ + h) * DK_;
    const float* kb = k + base;
    const float* qb = q + base;
    const float* vb = v + base;
    float*       ob = out + base;
    const float* gb = g_decay + (size_t)b * S_ * H_ + h;
    const float* bb = g_beta  + (size_t)b * S_ * H_ + h;

    u64 st[16];
    #pragma unroll
    for (int j = 0; j < 16; ++j) st[j] = 0ull;

    Buf A, Bf;
    load_buf(A,  kb, qb, vb, gb, bb, 0, sub, col);
    load_buf(Bf, kb, qb, vb, gb, bb, 1, sub, col);

    for (int s = 0; s < S_; s += 2) {
        do_step(A, st, ob + (size_t)s*(H_*DV_), sub, col);
        int i2 = (s+2 < S_) ? s+2 : S_-1;
        load_buf(A, kb, qb, vb, gb, bb, i2, sub, col);   // covered by step B
        do_step(Bf, st, ob + (size_t)(s+1)*(H_*DV_), sub, col);
        int i3 = (s+3 < S_) ? s+3 : S_-1;
        load_buf(Bf, kb, qb, vb, gb, bb, i3, sub, col);  // covered by next step A
    }
}

// ============================================================
extern "C" void kernel_launch(void* const* d_in, const int* in_sizes, int n_in,
                              void* d_out, int out_size)
{
    (void)in_sizes; (void)n_in; (void)out_size;
    const float* x   = (const float*)d_in[0];
    const float* q   = (const float*)d_in[1];
    const float* k   = (const float*)d_in[2];
    const float* v   = (const float*)d_in[3];
    const float* Wa  = (const float*)d_in[4];
    const float* Wb  = (const float*)d_in[5];
    const float* dtb = (const float*)d_in[6];
    const float* Al  = (const float*)d_in[7];
    float* out = (float*)d_out;

    gate_kernel<<<P_/GT_POS, 256>>>(x, Wa, Wb, dtb, Al);
    scan_kernel<<<B_*H_*(DV_/8), 32>>>(q, k, v, out);
}

// round 9
// speedup vs baseline: 1.9155x; 1.2186x over previous
#include <cuda_runtime.h>

#define B_   4
#define S_   2048
#define H_   16
#define HID_ 2048
#define DK_  128
#define DV_  128
#define P_   (B_*S_)   // 8192 positions

// scratch (allowed: __device__ globals)
__device__ float g_decay[P_*H_];
__device__ float g_beta [P_*H_];

// ============================================================
// Kernel 1: gating GEMM  raw = x @ [Wa;Wb]^T  + epilogue
// ============================================================
#define GT_POS 64
#define GT_K   32

__global__ __launch_bounds__(256) void gate_kernel(
    const float* __restrict__ x,
    const float* __restrict__ Wa, const float* __restrict__ Wb,
    const float* __restrict__ dt_bias, const float* __restrict__ A_log)
{
    __shared__ float xs[GT_POS][GT_K+1];
    __shared__ float ws[32][GT_K+1];
    int t  = threadIdx.x;
    int p0 = blockIdx.x * GT_POS;
    int tx = t & 7;
    int ty = t >> 3;
    float acc[2][4] = {};

    for (int kc = 0; kc < HID_; kc += GT_K) {
        #pragma unroll
        for (int i = 0; i < (GT_POS*GT_K)/256; ++i) {
            int e = i*256 + t; int r = e >> 5, c = e & 31;
            xs[r][c] = x[(size_t)(p0 + r)*HID_ + kc + c];
        }
        #pragma unroll
        for (int i = 0; i < (32*GT_K)/256; ++i) {
            int e = i*256 + t; int f = e >> 5, c = e & 31;
            const float* wrow = (f < 16) ? (Wa + f*HID_) : (Wb + (f-16)*HID_);
            ws[f][c] = wrow[kc + c];
        }
        __syncthreads();
        #pragma unroll
        for (int k = 0; k < GT_K; ++k) {
            float xv0 = xs[2*ty  ][k];
            float xv1 = xs[2*ty+1][k];
            #pragma unroll
            for (int j = 0; j < 4; ++j) {
                float wv = ws[4*tx+j][k];
                acc[0][j] = fmaf(xv0, wv, acc[0][j]);
                acc[1][j] = fmaf(xv1, wv, acc[1][j]);
            }
        }
        __syncthreads();
    }

    #pragma unroll
    for (int i = 0; i < 2; ++i) {
        int p = p0 + 2*ty + i;
        #pragma unroll
        for (int j = 0; j < 4; ++j) {
            int f = 4*tx + j;
            float r = acc[i][j];
            if (f < 16) {
                float z  = r + __ldg(dt_bias + f);
                float sp = fmaxf(z, 0.0f) + log1pf(expf(-fabsf(z)));
                g_decay[p*H_ + f] = expf(-expf(__ldg(A_log + f)) * sp);
            } else {
                g_beta[p*H_ + (f-16)] = r;
            }
        }
    }
}

// ============================================================
// Kernel 2: delta-rule scan with SMEM-broadcast k/q staging.
// CTA = 128 thr = (b, h, 32 DV cols); 256 CTAs, 1024 warps.
// Fill: per 2 steps each thread does ONE LDG.128 (coalesced) +
// ONE STS.128 with permutation perm(c) = (c&3)*8 + (c>>2), so the
// consumer LDS at slot (i*8 + lk) returns rows 16*lk + 4i .. +3.
// Consumer lane (lk = l&7, lv = l>>3) owns rows 16lk..+15 and
// cols (warp colbase + lv*2, +1). LDS.128 = 8 distinct 16B chunks
// broadcast 4-way -> conflict-free, unique-byte cost only.
// Step math identical to the proven R2 kernel:
//   p = k.S ; o = q.S ; qk = q.k  (reduced over lk: xor1,2,4)
//   d = (v - g*p)*beta ; S = g*S + k (x) d ; out = g*o + qk*d
// ============================================================
typedef unsigned long long u64;

__device__ __forceinline__ u64 fma2(u64 a, u64 b, u64 c) {
    u64 d; asm("fma.rn.f32x2 %0, %1, %2, %3;" : "=l"(d) : "l"(a), "l"(b), "l"(c));
    return d;
}
__device__ __forceinline__ u64 mul2(u64 a, u64 b) {
    u64 d; asm("mul.rn.f32x2 %0, %1, %2;" : "=l"(d) : "l"(a), "l"(b));
    return d;
}
__device__ __forceinline__ u64 pack2(float x, float y) {
    u64 d; asm("mov.b64 %0, {%1, %2};" : "=l"(d)
               : "r"(__float_as_uint(x)), "r"(__float_as_uint(y)));
    return d;
}
__device__ __forceinline__ float hadd2(u64 a) {
    unsigned lo, hi;
    asm("mov.b64 {%0, %1}, %2;" : "=r"(lo), "=r"(hi) : "l"(a));
    return __uint_as_float(lo) + __uint_as_float(hi);
}

struct PairPre {                 // prefetched v/g/beta for a step pair
    float2 v0, v1;
    float g0, b0, g1, b1;
};

__device__ __forceinline__ void load_pre(PairPre& p,
    const float* vb, const float* gb, const float* bb, int s, int vq)
{
    int s1 = (s + 1 < S_) ? s + 1 : S_ - 1;
    size_t o0 = (size_t)s  * (H_*DK_);
    size_t o1 = (size_t)s1 * (H_*DK_);
    p.v0 = __ldg((const float2*)(vb + o0) + vq);
    p.v1 = __ldg((const float2*)(vb + o1) + vq);
    p.g0 = __ldg(gb + (size_t)s  * H_);
    p.b0 = __ldg(bb + (size_t)s  * H_);
    p.g1 = __ldg(gb + (size_t)s1 * H_);
    p.b1 = __ldg(bb + (size_t)s1 * H_);
}

// compute one step from smem slot
__device__ __forceinline__ void do_step(const float4* kslot, const float4* qslot,
                                        u64 st[8][2], float2 vv, float g, float be,
                                        float* outp, int lk, int vhalf)
{
    u64 k2[8], q2[8];
    #pragma unroll
    for (int i = 0; i < 4; ++i) {
        ulonglong2 kk = *reinterpret_cast<const ulonglong2*>(kslot + i*8 + lk);
        k2[2*i] = kk.x; k2[2*i+1] = kk.y;
        ulonglong2 qq = *reinterpret_cast<const ulonglong2*>(qslot + i*8 + lk);
        q2[2*i] = qq.x; q2[2*i+1] = qq.y;
    }

    u64 p2a = 0, p2b = 0, o2a = 0, o2b = 0, qk2 = 0;
    #pragma unroll
    for (int j = 0; j < 8; ++j) {
        p2a = fma2(k2[j], st[j][0], p2a);
        p2b = fma2(k2[j], st[j][1], p2b);
        o2a = fma2(q2[j], st[j][0], o2a);
        o2b = fma2(q2[j], st[j][1], o2b);
        qk2 = fma2(q2[j], k2[j], qk2);
    }
    float p0 = hadd2(p2a), p1 = hadd2(p2b);
    float o0 = hadd2(o2a), o1 = hadd2(o2b);
    float qk = hadd2(qk2);
    #pragma unroll
    for (int m = 1; m < 8; m <<= 1) {
        p0 += __shfl_xor_sync(0xffffffffu, p0, m);
        p1 += __shfl_xor_sync(0xffffffffu, p1, m);
        o0 += __shfl_xor_sync(0xffffffffu, o0, m);
        o1 += __shfl_xor_sync(0xffffffffu, o1, m);
        qk += __shfl_xor_sync(0xffffffffu, qk, m);
    }
    float d0 = fmaf(-g, p0, vv.x) * be;
    float d1 = fmaf(-g, p1, vv.y) * be;
    u64 g2 = pack2(g, g), d0_2 = pack2(d0, d0), d1_2 = pack2(d1, d1);
    #pragma unroll
    for (int j = 0; j < 8; ++j) {
        st[j][0] = fma2(k2[j], d0_2, mul2(g2, st[j][0]));
        st[j][1] = fma2(k2[j], d1_2, mul2(g2, st[j][1]));
    }
    if (lk == 0) {
        float2 o;
        o.x = fmaf(g, o0, qk*d0);
        o.y = fmaf(g, o1, qk*d1);
        ((float2*)outp)[vhalf] = o;
    }
}

__global__ void __launch_bounds__(128) scan_kernel(
    const float* __restrict__ q, const float* __restrict__ k,
    const float* __restrict__ v, float* __restrict__ out)
{
    // smem ring: 4 step slots x {k,q} x 32 float4 (512B each region)
    __shared__ float4 sm[4*2*32];

    int bid    = blockIdx.x;         // 256 CTAs
    int colcta = bid & 3;            // 4 col-CTAs of 32 cols
    int bh     = bid >> 2;
    int b      = bh >> 4, h = bh & 15;
    int tid    = threadIdx.x;
    int w      = tid >> 5;           // warp 0..3
    int lane   = tid & 31;
    int lk     = lane & 7, lv = lane >> 3;
    int col0   = colcta*32 + w*8 + lv*2;   // lane's first DV col
    int vq     = col0 >> 1;                // float2 index

    size_t base = ((size_t)b * S_ * H_ + h) * DK_;
    const float* kb = k + base;
    const float* qb = q + base;
    const float* vb = v + base;
    float*       ob = out + base;
    const float* gb = g_decay + (size_t)b * S_ * H_ + h;
    const float* bb = g_beta  + (size_t)b * S_ * H_ + h;

    // fill params: thread covers (vecsel = tid>>5, c = tid&31)
    int vecsel = tid >> 5;           // 0:k@f0 1:q@f0 2:k@f1 3:q@f1
    int c      = tid & 31;
    int perm   = ((c & 3) << 3) | (c >> 2);
    const float* fsrc = (vecsel & 1) ? qb : kb;
    int fstep_off = vecsel >> 1;     // 0 or 1
    // destination base index (vec region) resolved per fill by slot

    // ---- pre-fill steps 0..3 ----
    #pragma unroll
    for (int f0 = 0; f0 < 4; f0 += 2) {
        int fs = f0 + fstep_off;
        float4 val = __ldg((const float4*)(fsrc + (size_t)fs*(H_*DK_)) + c);
        sm[((fs & 3)*2 + (vecsel & 1))*32 + perm] = val;
    }
    __syncthreads();

    u64 st[8][2];
    #pragma unroll
    for (int j = 0; j < 8; ++j) { st[j][0] = 0ull; st[j][1] = 0ull; }

    PairPre Pc, Pn;
    load_pre(Pc, vb, gb, bb, 0, vq);

    for (int s = 0; s < S_; s += 2) {
        // prefetch next pair's v/g/b
        int sp = (s + 2 < S_) ? s + 2 : S_ - 2;
        load_pre(Pn, vb, gb, bb, sp, vq);

        const float4* k0 = &sm[((s & 3)*2 + 0)*32];
        const float4* q0 = &sm[((s & 3)*2 + 1)*32];
        do_step(k0, q0, st, Pc.v0, Pc.g0, Pc.b0,
                ob + (size_t)s*(H_*DV_), lk, vq);

        const float4* k1 = &sm[(((s+1) & 3)*2 + 0)*32];
        const float4* q1 = &sm[(((s+1) & 3)*2 + 1)*32];
        do_step(k1, q1, st, Pc.v1, Pc.g1, Pc.b1,
                ob + (size_t)(s+1)*(H_*DV_), lk, vq);

        __syncthreads();   // compute(s,s+1) done -> safe to overwrite slots

        // fill steps s+4, s+5 into slots (s&3), (s+1&3)
        {
            int fs = s + 4 + fstep_off;
            if (fs > S_ - 1) fs = S_ - 1;
            float4 val = __ldg((const float4*)(fsrc + (size_t)fs*(H_*DK_)) + c);
            sm[(((s + 4 + fstep_off) & 3)*2 + (vecsel & 1))*32 + perm] = val;
        }
        // no second sync needed: next iter reads slots (s+2)&3,(s+3)&3,
        // untouched by this fill; RAW for s+4 is covered by iter s+2's sync.

        Pc = Pn;
    }
}

// ============================================================
extern "C" void kernel_launch(void* const* d_in, const int* in_sizes, int n_in,
                              void* d_out, int out_size)
{
    (void)in_sizes; (void)n_in; (void)out_size;
    const float* x   = (const float*)d_in[0];
    const float* q   = (const float*)d_in[1];
    const float* k   = (const float*)d_in[2];
    const float* v   = (const float*)d_in[3];
    const float* Wa  = (const float*)d_in[4];
    const float* Wb  = (const float*)d_in[5];
    const float* dtb = (const float*)d_in[6];
    const float* Al  = (const float*)d_in[7];
    float* out = (float*)d_out;

    gate_kernel<<<P_/GT_POS, 256>>>(x, Wa, Wb, dtb, Al);
    scan_kernel<<<B_*H_*4, 128>>>(q, k, v, out);
}

// round 10
// speedup vs baseline: 2.7773x; 1.4499x over previous
#include <cuda_runtime.h>

#define B_   4
#define S_   2048
#define H_   16
#define HID_ 2048
#define DK_  128
#define DV_  128
#define P_   (B_*S_)   // 8192 positions

// scratch (allowed: __device__ globals)
__device__ float g_decay[P_*H_];
__device__ float g_beta [P_*H_];

// ============================================================
// Kernel 1: gating GEMM  raw = x @ [Wa;Wb]^T  + epilogue
// ============================================================
#define GT_POS 64
#define GT_K   32

__global__ __launch_bounds__(256) void gate_kernel(
    const float* __restrict__ x,
    const float* __restrict__ Wa, const float* __restrict__ Wb,
    const float* __restrict__ dt_bias, const float* __restrict__ A_log)
{
    __shared__ float xs[GT_POS][GT_K+1];
    __shared__ float ws[32][GT_K+1];
    int t  = threadIdx.x;
    int p0 = blockIdx.x * GT_POS;
    int tx = t & 7;
    int ty = t >> 3;
    float acc[2][4] = {};

    for (int kc = 0; kc < HID_; kc += GT_K) {
        #pragma unroll
        for (int i = 0; i < (GT_POS*GT_K)/256; ++i) {
            int e = i*256 + t; int r = e >> 5, c = e & 31;
            xs[r][c] = x[(size_t)(p0 + r)*HID_ + kc + c];
        }
        #pragma unroll
        for (int i = 0; i < (32*GT_K)/256; ++i) {
            int e = i*256 + t; int f = e >> 5, c = e & 31;
            const float* wrow = (f < 16) ? (Wa + f*HID_) : (Wb + (f-16)*HID_);
            ws[f][c] = wrow[kc + c];
        }
        __syncthreads();
        #pragma unroll
        for (int k = 0; k < GT_K; ++k) {
            float xv0 = xs[2*ty  ][k];
            float xv1 = xs[2*ty+1][k];
            #pragma unroll
            for (int j = 0; j < 4; ++j) {
                float wv = ws[4*tx+j][k];
                acc[0][j] = fmaf(xv0, wv, acc[0][j]);
                acc[1][j] = fmaf(xv1, wv, acc[1][j]);
            }
        }
        __syncthreads();
    }

    #pragma unroll
    for (int i = 0; i < 2; ++i) {
        int p = p0 + 2*ty + i;
        #pragma unroll
        for (int j = 0; j < 4; ++j) {
            int f = 4*tx + j;
            float r = acc[i][j];
            if (f < 16) {
                float z  = r + __ldg(dt_bias + f);
                float sp = fmaxf(z, 0.0f) + log1pf(expf(-fabsf(z)));
                g_decay[p*H_ + f] = expf(-expf(__ldg(A_log + f)) * sp);
            } else {
                g_beta[p*H_ + (f-16)] = r;
            }
        }
    }
}

// ============================================================
// Kernel 2: delta-rule scan. SMEM-broadcast k/q staging + high
// warp count.  CTA = 256 thr = 8 warps; warp w owns 4 DV cols
// (colbase = colcta*32 + w*4); grid = 64 bh x 4 colcta = 256.
// Lane = (rg = lane>>2 owns rows 16rg..+15, co = lane&3 owns
// col colbase+co). State: 8 u64 (16 rows x 1 col).
// Fill (R9-verified): per 2 steps, threads 0..127 do one
// LDG.128 + STS.128 with perm(c) = (c&3)*8 + (c>>2); consumer
// LDS at index i*8+rg returns rows 16rg+4i..+3 (4-way co
// broadcast, conflict-free).
// Per step:
//   p = redux8( k . S[:,col] )      (hadd + xor4,8,16)
//   d = (v - g*p) * beta
//   S = g*S + k (x) d
//   o = redux8( q . S_new[:,col] )  (off recurrence path)
// ============================================================
typedef unsigned long long u64;

__device__ __forceinline__ u64 fma2(u64 a, u64 b, u64 c) {
    u64 d; asm("fma.rn.f32x2 %0, %1, %2, %3;" : "=l"(d) : "l"(a), "l"(b), "l"(c));
    return d;
}
__device__ __forceinline__ u64 mul2(u64 a, u64 b) {
    u64 d; asm("mul.rn.f32x2 %0, %1, %2;" : "=l"(d) : "l"(a), "l"(b));
    return d;
}
__device__ __forceinline__ u64 pack2(float x, float y) {
    u64 d; asm("mov.b64 %0, {%1, %2};" : "=l"(d)
               : "r"(__float_as_uint(x)), "r"(__float_as_uint(y)));
    return d;
}
__device__ __forceinline__ float hadd2(u64 a) {
    unsigned lo, hi;
    asm("mov.b64 {%0, %1}, %2;" : "=r"(lo), "=r"(hi) : "l"(a));
    return __uint_as_float(lo) + __uint_as_float(hi);
}

struct PairPre {                 // prefetched v/g/beta for a step pair
    float v0, v1;
    float g0, b0, g1, b1;
};

__device__ __forceinline__ void load_pre(PairPre& p,
    const float* vb, const float* gb, const float* bb, int s, int col)
{
    int s1 = (s + 1 < S_) ? s + 1 : S_ - 1;
    p.v0 = __ldg(vb + (size_t)s  * (H_*DK_) + col);
    p.v1 = __ldg(vb + (size_t)s1 * (H_*DK_) + col);
    p.g0 = __ldg(gb + (size_t)s  * H_);
    p.b0 = __ldg(bb + (size_t)s  * H_);
    p.g1 = __ldg(gb + (size_t)s1 * H_);
    p.b1 = __ldg(bb + (size_t)s1 * H_);
}

__device__ __forceinline__ void do_step(const float4* kslot, const float4* qslot,
                                        u64 st[8], float v, float g, float be,
                                        float* outp, int rg, int col)
{
    const unsigned FM = 0xffffffffu;
    u64 k2[8], q2[8];
    #pragma unroll
    for (int i = 0; i < 4; ++i) {
        ulonglong2 kk = *reinterpret_cast<const ulonglong2*>(kslot + i*8 + rg);
        k2[2*i] = kk.x; k2[2*i+1] = kk.y;
        ulonglong2 qq = *reinterpret_cast<const ulonglong2*>(qslot + i*8 + rg);
        q2[2*i] = qq.x; q2[2*i+1] = qq.y;
    }

    // ---- p = k . S[:,col] ----
    u64 pa = mul2(k2[0], st[0]);
    u64 pb = mul2(k2[1], st[1]);
    #pragma unroll
    for (int j = 2; j < 8; j += 2) {
        pa = fma2(k2[j],   st[j],   pa);
        pb = fma2(k2[j+1], st[j+1], pb);
    }
    float p = hadd2(pa) + hadd2(pb);
    p += __shfl_xor_sync(FM, p, 4);
    p += __shfl_xor_sync(FM, p, 8);
    p += __shfl_xor_sync(FM, p, 16);

    // ---- delta ----
    float d = fmaf(-g, p, v) * be;

    // ---- state update: S = g*S + k (x) d ----
    u64 gp = pack2(g, g), dp = pack2(d, d);
    #pragma unroll
    for (int j = 0; j < 8; ++j)
        st[j] = fma2(k2[j], dp, mul2(gp, st[j]));

    // ---- o = q . S_new[:,col] (off recurrence critical path) ----
    u64 oa = mul2(q2[0], st[0]);
    u64 ob = mul2(q2[1], st[1]);
    #pragma unroll
    for (int j = 2; j < 8; j += 2) {
        oa = fma2(q2[j],   st[j],   oa);
        ob = fma2(q2[j+1], st[j+1], ob);
    }
    float o = hadd2(oa) + hadd2(ob);
    o += __shfl_xor_sync(FM, o, 4);
    o += __shfl_xor_sync(FM, o, 8);
    o += __shfl_xor_sync(FM, o, 16);

    if (rg == 0)
        outp[col] = o;
}

__global__ void __launch_bounds__(256, 2) scan_kernel(
    const float* __restrict__ q, const float* __restrict__ k,
    const float* __restrict__ v, float* __restrict__ out)
{
    // smem ring: 4 step slots x {k,q} x 32 float4
    __shared__ float4 sm[4*2*32];

    int bid    = blockIdx.x;         // 256 CTAs
    int colcta = bid & 3;            // 32-col slice
    int bh     = bid >> 2;
    int b      = bh >> 4, h = bh & 15;
    int tid    = threadIdx.x;
    int w      = tid >> 5;           // warp 0..7
    int lane   = tid & 31;
    int rg     = lane >> 2;          // 0..7 row group (16 rows)
    int co     = lane & 3;           // col owner
    int col    = colcta*32 + w*4 + co;

    size_t base = ((size_t)b * S_ * H_ + h) * DK_;
    const float* kb = k + base;
    const float* qb = q + base;
    const float* vb = v + base;
    float*       ob = out + base;
    const float* gb = g_decay + (size_t)b * S_ * H_ + h;
    const float* bb = g_beta  + (size_t)b * S_ * H_ + h;

    // fill params (threads 0..127 only)
    int vecsel = tid >> 5;           // 0:k@+0 1:q@+0 2:k@+1 3:q@+1
    int c      = tid & 31;
    int perm   = ((c & 3) << 3) | (c >> 2);
    const float* fsrc = (vecsel & 1) ? qb : kb;
    int fstep_off = (vecsel >> 1) & 1;
    bool filler = (tid < 128);

    // ---- pre-fill steps 0..3 ----
    if (filler) {
        #pragma unroll
        for (int f0 = 0; f0 < 4; f0 += 2) {
            int fs = f0 + fstep_off;
            float4 val = __ldg((const float4*)(fsrc + (size_t)fs*(H_*DK_)) + c);
            sm[((fs & 3)*2 + (vecsel & 1))*32 + perm] = val;
        }
    }
    __syncthreads();

    u64 st[8];
    #pragma unroll
    for (int j = 0; j < 8; ++j) st[j] = 0ull;

    PairPre Pc, Pn;
    load_pre(Pc, vb, gb, bb, 0, col);

    for (int s = 0; s < S_; s += 2) {
        int sp = (s + 2 < S_) ? s + 2 : S_ - 2;
        load_pre(Pn, vb, gb, bb, sp, col);

        const float4* k0 = &sm[((s & 3)*2 + 0)*32];
        const float4* q0 = &sm[((s & 3)*2 + 1)*32];
        do_step(k0, q0, st, Pc.v0, Pc.g0, Pc.b0,
                ob + (size_t)s*(H_*DV_), rg, col);

        const float4* k1 = &sm[(((s+1) & 3)*2 + 0)*32];
        const float4* q1 = &sm[(((s+1) & 3)*2 + 1)*32];
        do_step(k1, q1, st, Pc.v1, Pc.g1, Pc.b1,
                ob + (size_t)(s+1)*(H_*DV_), rg, col);

        __syncthreads();   // compute(s,s+1) done -> safe to overwrite slots

        if (filler) {
            int fs = s + 4 + fstep_off;
            if (fs > S_ - 1) fs = S_ - 1;
            float4 val = __ldg((const float4*)(fsrc + (size_t)fs*(H_*DK_)) + c);
            sm[(((s + 4 + fstep_off) & 3)*2 + (vecsel & 1))*32 + perm] = val;
        }
        // next iter reads slots (s+2)&3,(s+3)&3 (untouched by this fill);
        // fill(s+4) vs compute(s+4) is ordered by the barrier in iter s+2.

        Pc = Pn;
    }
}

// ============================================================
extern "C" void kernel_launch(void* const* d_in, const int* in_sizes, int n_in,
                              void* d_out, int out_size)
{
    (void)in_sizes; (void)n_in; (void)out_size;
    const float* x   = (const float*)d_in[0];
    const float* q   = (const float*)d_in[1];
    const float* k   = (const float*)d_in[2];
    const float* v   = (const float*)d_in[3];
    const float* Wa  = (const float*)d_in[4];
    const float* Wb  = (const float*)d_in[5];
    const float* dtb = (const float*)d_in[6];
    const float* Al  = (const float*)d_in[7];
    float* out = (float*)d_out;

    gate_kernel<<<P_/GT_POS, 256>>>(x, Wa, Wb, dtb, Al);
    scan_kernel<<<B_*H_*4, 256>>>(q, k, v, out);
}